// round 1
// baseline (speedup 1.0000x reference)
#include <cuda_runtime.h>
#include <cuda_bf16.h>
#include <cstdint>

// ---------------- constants ----------------
#define NROWS   8192          // 2N
#define NHALF   4096          // N
#define DIM     128
#define STRIDE  68            // smem row stride in 32-bit words (64 data + 4 pad, conflict-free)
#define NCHUNK  8             // j-chunks (grid.y)
#define TILES_PER_CHUNK 8     // 8 x 128 = 1024 j per chunk
#define SMEM_BYTES (2 * 128 * STRIDE * 4)
#define LOG2E_T 2.8853900817779268f   // 2 / ln(2): exp(2*s) = 2^(s * LOG2E_T)

// ---------------- device scratch (no allocation allowed) ----------------
__device__ float         g_repsf[NROWS * DIM];     // fp32 normalized (for positives)
__device__ __nv_bfloat16 g_repsb[NROWS * DIM];     // bf16 normalized (for GEMM)
__device__ float         g_posT[NHALF];            // pos / T
__device__ float         g_partial[16 * NROWS];    // (chunk*2 + warp_n) x row partial denoms

// ---------------- helpers ----------------
__device__ __forceinline__ float ex2f(float x) {
    float y;
    asm("ex2.approx.f32 %0, %1;" : "=f"(y) : "f"(x));
    return y;
}

__device__ __forceinline__ void mma16816(float* c, const uint32_t* a, uint32_t b0, uint32_t b1) {
    asm volatile(
        "mma.sync.aligned.m16n8k16.row.col.f32.bf16.bf16.f32 "
        "{%0,%1,%2,%3}, {%4,%5,%6,%7}, {%8,%9}, {%0,%1,%2,%3};\n"
        : "+f"(c[0]), "+f"(c[1]), "+f"(c[2]), "+f"(c[3])
        : "r"(a[0]), "r"(a[1]), "r"(a[2]), "r"(a[3]), "r"(b0), "r"(b1));
}

// ---------------- kernel 1: L2 normalize, write fp32 + bf16 ----------------
__global__ void normalize_kernel(const float* __restrict__ p1, const float* __restrict__ p2) {
    int row  = blockIdx.x * 8 + (threadIdx.x >> 5);
    int lane = threadIdx.x & 31;
    const float* src = (row < NHALF) ? (p1 + (size_t)row * DIM)
                                     : (p2 + (size_t)(row - NHALF) * DIM);
    float4 v = ((const float4*)src)[lane];
    float ss = v.x * v.x + v.y * v.y + v.z * v.z + v.w * v.w;
#pragma unroll
    for (int o = 16; o > 0; o >>= 1) ss += __shfl_xor_sync(0xffffffffu, ss, o);
    float inv = 1.0f / fmaxf(sqrtf(ss), 1e-12f);
    v.x *= inv; v.y *= inv; v.z *= inv; v.w *= inv;
    ((float4*)(g_repsf + (size_t)row * DIM))[lane] = v;
    __nv_bfloat162 b0 = __floats2bfloat162_rn(v.x, v.y);
    __nv_bfloat162 b1 = __floats2bfloat162_rn(v.z, v.w);
    uint2 u;
    u.x = *(uint32_t*)&b0;
    u.y = *(uint32_t*)&b1;
    ((uint2*)(g_repsb + (size_t)row * DIM))[lane] = u;
}

// ---------------- kernel 2: positives (fp32 dots of paired rows) ----------------
__global__ void pos_kernel() {
    int i    = blockIdx.x * 8 + (threadIdx.x >> 5);   // 0..4095
    int lane = threadIdx.x & 31;
    float4 a = ((const float4*)(g_repsf + (size_t)i * DIM))[lane];
    float4 b = ((const float4*)(g_repsf + (size_t)(i + NHALF) * DIM))[lane];
    float d = a.x * b.x + a.y * b.y + a.z * b.z + a.w * b.w;
#pragma unroll
    for (int o = 16; o > 0; o >>= 1) d += __shfl_xor_sync(0xffffffffu, d, o);
    if (lane == 0) g_posT[i] = d * 2.0f;   // pos / T, T = 0.5
}

// ---------------- kernel 3: gram tile + exp + masked row-sums ----------------
// grid: (64, 8)  block: 256 (8 warps). CTA tile: 128 rows x (8 x 128) cols.
// Warp layout: warp_m = warp/2 (4), warp_n = warp%2 (2); warp tile 32 x 64.
__global__ __launch_bounds__(256) void sim_kernel() {
    extern __shared__ uint32_t sm[];
    uint32_t* As = sm;
    uint32_t* Bs = sm + 128 * STRIDE;

    int tid  = threadIdx.x;
    int warp = tid >> 5, lane = tid & 31;
    int wm = warp >> 1, wn = warp & 1;
    int gid = lane >> 2, t4 = lane & 3;
    int i0    = blockIdx.x * 128;
    int chunk = blockIdx.y;

    // load A tile (rows i0..i0+127), 128-bit vectorized, padded smem
    {
        const uint4* ga = (const uint4*)(g_repsb + (size_t)i0 * DIM);
#pragma unroll
        for (int it = 0; it < 8; it++) {
            int idx = tid + it * 256;       // 0..2047
            int r = idx >> 4, c = idx & 15;
            *(uint4*)&As[r * STRIDE + c * 4] = ga[idx];
        }
    }

    float rs[2][2] = {{0.f, 0.f}, {0.f, 0.f}};   // per-thread row sums [mf][half]

    for (int jt = 0; jt < TILES_PER_CHUNK; jt++) {
        int j0 = chunk * 1024 + jt * 128;
        __syncthreads();   // prev tile consumed (and A visible on first iter)
        {
            const uint4* gb = (const uint4*)(g_repsb + (size_t)j0 * DIM);
#pragma unroll
            for (int it = 0; it < 8; it++) {
                int idx = tid + it * 256;
                int r = idx >> 4, c = idx & 15;
                *(uint4*)&Bs[r * STRIDE + c * 4] = gb[idx];
            }
        }
        __syncthreads();

        float acc[2][8][4];
#pragma unroll
        for (int mf = 0; mf < 2; mf++)
#pragma unroll
            for (int nf = 0; nf < 8; nf++)
#pragma unroll
                for (int q = 0; q < 4; q++) acc[mf][nf][q] = 0.f;

#pragma unroll
        for (int k = 0; k < 8; k++) {     // k16 steps over K=128
            int k8 = k * 8;
            uint32_t a[2][4];
#pragma unroll
            for (int mf = 0; mf < 2; mf++) {
                int ar = wm * 32 + mf * 16 + gid;
                a[mf][0] = As[ar * STRIDE + k8 + t4];
                a[mf][1] = As[(ar + 8) * STRIDE + k8 + t4];
                a[mf][2] = As[ar * STRIDE + k8 + t4 + 4];
                a[mf][3] = As[(ar + 8) * STRIDE + k8 + t4 + 4];
            }
#pragma unroll
            for (int nf = 0; nf < 8; nf++) {
                int br = wn * 64 + nf * 8 + gid;
                uint32_t b0 = Bs[br * STRIDE + k8 + t4];
                uint32_t b1 = Bs[br * STRIDE + k8 + t4 + 4];
#pragma unroll
                for (int mf = 0; mf < 2; mf++)
                    mma16816(acc[mf][nf], a[mf], b0, b1);
            }
        }

        // epilogue: exp(2*sim) with diagonal masked, accumulate row sums
        bool isdiag = (j0 == i0);
#pragma unroll
        for (int mf = 0; mf < 2; mf++)
#pragma unroll
            for (int h = 0; h < 2; h++) {
                int rowg = i0 + wm * 32 + mf * 16 + h * 8 + gid;
                float s = 0.f;
#pragma unroll
                for (int nf = 0; nf < 8; nf++) {
                    int colg = j0 + wn * 64 + nf * 8 + t4 * 2;
                    float e0 = ex2f(acc[mf][nf][h * 2]     * LOG2E_T);
                    float e1 = ex2f(acc[mf][nf][h * 2 + 1] * LOG2E_T);
                    if (isdiag) {
                        if (rowg == colg)     e0 = 0.f;
                        if (rowg == colg + 1) e1 = 0.f;
                    }
                    s += e0 + e1;
                }
                rs[mf][h] += s;
            }
    }

    // reduce quad (cols) and store deterministic partial: one writer per slot
#pragma unroll
    for (int mf = 0; mf < 2; mf++)
#pragma unroll
        for (int h = 0; h < 2; h++) {
            float v = rs[mf][h];
            v += __shfl_xor_sync(0xffffffffu, v, 1);
            v += __shfl_xor_sync(0xffffffffu, v, 2);
            if (t4 == 0) {
                int rowg = i0 + wm * 32 + mf * 16 + h * 8 + gid;
                g_partial[(chunk * 2 + wn) * NROWS + rowg] = v;
            }
        }
}

// ---------------- kernel 4: finalize ----------------
__global__ void finalize_kernel(float* __restrict__ out) {
    __shared__ float red[256];
    int tid = threadIdx.x;
    float a = 0.f;
    for (int r = tid; r < NROWS; r += 256) {
        float d = 0.f;
#pragma unroll
        for (int p = 0; p < 16; p++) d += g_partial[p * NROWS + r];
        a += logf(d) - g_posT[r & (NHALF - 1)];
    }
    red[tid] = a;
    __syncthreads();
    for (int s = 128; s > 0; s >>= 1) {
        if (tid < s) red[tid] += red[tid + s];
        __syncthreads();
    }
    if (tid == 0) out[0] = red[0] / (float)NROWS;
}

// ---------------- launch ----------------
extern "C" void kernel_launch(void* const* d_in, const int* in_sizes, int n_in,
                              void* d_out, int out_size) {
    const float* p1 = (const float*)d_in[0];
    const float* p2 = (const float*)d_in[1];
    float* out = (float*)d_out;

    cudaFuncSetAttribute(sim_kernel, cudaFuncAttributeMaxDynamicSharedMemorySize, SMEM_BYTES);

    normalize_kernel<<<NROWS / 8, 256>>>(p1, p2);
    pos_kernel<<<NHALF / 8, 256>>>();
    sim_kernel<<<dim3(64, NCHUNK), 256, SMEM_BYTES>>>();
    finalize_kernel<<<1, 256>>>(out);
}

// round 2
// speedup vs baseline: 2.0256x; 2.0256x over previous
#include <cuda_runtime.h>
#include <cuda_bf16.h>
#include <cstdint>

// ---------------- constants ----------------
#define NROWS   8192          // 2N
#define NHALF   4096          // N
#define DIM     128
#define NT      64            // number of 128-row tiles
#define NTILES  2080          // NT*(NT+1)/2 upper-triangle tile pairs
#define STRIDE  68            // smem row stride in words (64 data + 4 pad)
#define SMEM_BYTES (2 * 128 * STRIDE * 4)
#define LOG2E_T 2.8853900817779268f   // 2/ln(2): exp(2*s) = 2^(s*LOG2E_T)

// ---------------- device scratch ----------------
__device__ float         g_repsf[NROWS * DIM];
__device__ __nv_bfloat16 g_repsb[NROWS * DIM];
__device__ float         g_posT[NHALF];
__device__ float         g_partial[NT * NROWS];   // [other-tile][row], each slot written once
__device__ float         g_blocksum[32];

// ---------------- helpers ----------------
__device__ __forceinline__ float ex2f(float x) {
    float y;
    asm("ex2.approx.f32 %0, %1;" : "=f"(y) : "f"(x));
    return y;
}

__device__ __forceinline__ void mma16816(float* c, const uint32_t* a, uint32_t b0, uint32_t b1) {
    asm volatile(
        "mma.sync.aligned.m16n8k16.row.col.f32.bf16.bf16.f32 "
        "{%0,%1,%2,%3}, {%4,%5,%6,%7}, {%8,%9}, {%0,%1,%2,%3};\n"
        : "+f"(c[0]), "+f"(c[1]), "+f"(c[2]), "+f"(c[3])
        : "r"(a[0]), "r"(a[1]), "r"(a[2]), "r"(a[3]), "r"(b0), "r"(b1));
}

// ---------------- kernel 1: L2 normalize ----------------
__global__ void normalize_kernel(const float* __restrict__ p1, const float* __restrict__ p2) {
    int row  = blockIdx.x * 8 + (threadIdx.x >> 5);
    int lane = threadIdx.x & 31;
    const float* src = (row < NHALF) ? (p1 + (size_t)row * DIM)
                                     : (p2 + (size_t)(row - NHALF) * DIM);
    float4 v = ((const float4*)src)[lane];
    float ss = v.x * v.x + v.y * v.y + v.z * v.z + v.w * v.w;
#pragma unroll
    for (int o = 16; o > 0; o >>= 1) ss += __shfl_xor_sync(0xffffffffu, ss, o);
    float inv = 1.0f / fmaxf(sqrtf(ss), 1e-12f);
    v.x *= inv; v.y *= inv; v.z *= inv; v.w *= inv;
    ((float4*)(g_repsf + (size_t)row * DIM))[lane] = v;
    __nv_bfloat162 b0 = __floats2bfloat162_rn(v.x, v.y);
    __nv_bfloat162 b1 = __floats2bfloat162_rn(v.z, v.w);
    uint2 u;
    u.x = *(uint32_t*)&b0;
    u.y = *(uint32_t*)&b1;
    ((uint2*)(g_repsb + (size_t)row * DIM))[lane] = u;
}

// ---------------- kernel 2: positives ----------------
__global__ void pos_kernel() {
    int i    = blockIdx.x * 8 + (threadIdx.x >> 5);
    int lane = threadIdx.x & 31;
    float4 a = ((const float4*)(g_repsf + (size_t)i * DIM))[lane];
    float4 b = ((const float4*)(g_repsf + (size_t)(i + NHALF) * DIM))[lane];
    float d = a.x * b.x + a.y * b.y + a.z * b.z + a.w * b.w;
#pragma unroll
    for (int o = 16; o > 0; o >>= 1) d += __shfl_xor_sync(0xffffffffu, d, o);
    if (lane == 0) g_posT[i] = d * 2.0f;
}

// ---------------- kernel 3: upper-triangle tile -> exp -> row+col sums ----------------
// grid: 2080 CTAs (one 128x128 tile each), block 256 (8 warps, 4 wm x 2 wn).
__global__ __launch_bounds__(256) void sim_kernel() {
    extern __shared__ uint32_t sm[];
    uint32_t* As = sm;
    uint32_t* Bs = sm + 128 * STRIDE;
    __shared__ float rowpart[2][128];
    __shared__ float colpart[4][128];

    int tid  = threadIdx.x;
    int warp = tid >> 5, lane = tid & 31;
    int wm = warp >> 1, wn = warp & 1;
    int gid = lane >> 2, t4 = lane & 3;

    // decode upper-triangle pair (ti <= tj) from linear block id
    int b = blockIdx.x;
    int ti = (int)((129.0f - sqrtf(16641.0f - 8.0f * (float)b)) * 0.5f);
#define FROW(t) ((t) * NT - (t) * ((t) - 1) / 2)
    while (FROW(ti + 1) <= b) ti++;
    while (FROW(ti) > b) ti--;
    int tj = ti + (b - FROW(ti));
    int i0 = ti * 128, j0 = tj * 128;
    bool isdiag = (ti == tj);

    // load A tile (and B tile if off-diagonal; diag reuses A)
    {
        const uint4* ga = (const uint4*)(g_repsb + (size_t)i0 * DIM);
#pragma unroll
        for (int it = 0; it < 8; it++) {
            int idx = tid + it * 256;
            int r = idx >> 4, c = idx & 15;
            *(uint4*)&As[r * STRIDE + c * 4] = ga[idx];
        }
    }
    if (!isdiag) {
        const uint4* gb = (const uint4*)(g_repsb + (size_t)j0 * DIM);
#pragma unroll
        for (int it = 0; it < 8; it++) {
            int idx = tid + it * 256;
            int r = idx >> 4, c = idx & 15;
            *(uint4*)&Bs[r * STRIDE + c * 4] = gb[idx];
        }
    }
    __syncthreads();
    uint32_t* Bp = isdiag ? As : Bs;

    float acc[2][8][4];
#pragma unroll
    for (int mf = 0; mf < 2; mf++)
#pragma unroll
        for (int nf = 0; nf < 8; nf++)
#pragma unroll
            for (int q = 0; q < 4; q++) acc[mf][nf][q] = 0.f;

#pragma unroll
    for (int k = 0; k < 8; k++) {
        int k8 = k * 8;
        uint32_t a[2][4];
#pragma unroll
        for (int mf = 0; mf < 2; mf++) {
            int ar = wm * 32 + mf * 16 + gid;
            a[mf][0] = As[ar * STRIDE + k8 + t4];
            a[mf][1] = As[(ar + 8) * STRIDE + k8 + t4];
            a[mf][2] = As[ar * STRIDE + k8 + t4 + 4];
            a[mf][3] = As[(ar + 8) * STRIDE + k8 + t4 + 4];
        }
#pragma unroll
        for (int nf = 0; nf < 8; nf++) {
            int br = wn * 64 + nf * 8 + gid;
            uint32_t b0 = Bp[br * STRIDE + k8 + t4];
            uint32_t b1 = Bp[br * STRIDE + k8 + t4 + 4];
#pragma unroll
            for (int mf = 0; mf < 2; mf++)
                mma16816(acc[mf][nf], a[mf], b0, b1);
        }
    }

    // epilogue: exp(2*sim), diag masked; accumulate row sums + col sums
    float rs[2][2] = {{0.f, 0.f}, {0.f, 0.f}};
    float cs[8][2];
#pragma unroll
    for (int nf = 0; nf < 8; nf++) { cs[nf][0] = 0.f; cs[nf][1] = 0.f; }

#pragma unroll
    for (int mf = 0; mf < 2; mf++)
#pragma unroll
        for (int h = 0; h < 2; h++) {
            int rowg = i0 + wm * 32 + mf * 16 + h * 8 + gid;
            float s = 0.f;
#pragma unroll
            for (int nf = 0; nf < 8; nf++) {
                int colg = j0 + wn * 64 + nf * 8 + t4 * 2;
                float e0 = ex2f(acc[mf][nf][h * 2]     * LOG2E_T);
                float e1 = ex2f(acc[mf][nf][h * 2 + 1] * LOG2E_T);
                if (isdiag) {
                    if (rowg == colg)     e0 = 0.f;
                    if (rowg == colg + 1) e1 = 0.f;
                }
                s += e0 + e1;
                cs[nf][0] += e0;
                cs[nf][1] += e1;
            }
            rs[mf][h] += s;
        }

    // row sums: quad-reduce over cols, per-wn halves into smem
#pragma unroll
    for (int mf = 0; mf < 2; mf++)
#pragma unroll
        for (int h = 0; h < 2; h++) {
            float v = rs[mf][h];
            v += __shfl_xor_sync(0xffffffffu, v, 1);
            v += __shfl_xor_sync(0xffffffffu, v, 2);
            if (t4 == 0)
                rowpart[wn][wm * 32 + mf * 16 + h * 8 + gid] = v;
        }

    // col sums (off-diag only): reduce across gid lanes, per-wm rows into smem
    if (!isdiag) {
#pragma unroll
        for (int nf = 0; nf < 8; nf++)
#pragma unroll
            for (int c = 0; c < 2; c++) {
                float u = cs[nf][c];
                u += __shfl_xor_sync(0xffffffffu, u, 4);
                u += __shfl_xor_sync(0xffffffffu, u, 8);
                u += __shfl_xor_sync(0xffffffffu, u, 16);
                if (gid == 0)
                    colpart[wm][wn * 64 + nf * 8 + t4 * 2 + c] = u;
            }
    }
    __syncthreads();

    if (tid < 128) {
        float rv = rowpart[0][tid] + rowpart[1][tid];
        g_partial[(size_t)tj * NROWS + i0 + tid] = rv;   // rows of tile ti, slot tj
        if (!isdiag) {
            float cv = colpart[0][tid] + colpart[1][tid] + colpart[2][tid] + colpart[3][tid];
            g_partial[(size_t)ti * NROWS + j0 + tid] = cv;  // rows of tile tj, slot ti
        }
    }
}

// ---------------- kernel 4a: per-row log, block partial sums ----------------
__global__ void finalize1_kernel() {
    __shared__ float red[256];
    int tid = threadIdx.x;
    int r = blockIdx.x * 256 + tid;
    float d = 0.f;
#pragma unroll
    for (int p = 0; p < NT; p++) d += g_partial[p * NROWS + r];
    float a = logf(d) - g_posT[r & (NHALF - 1)];
    red[tid] = a;
    __syncthreads();
    for (int s = 128; s > 0; s >>= 1) {
        if (tid < s) red[tid] += red[tid + s];
        __syncthreads();
    }
    if (tid == 0) g_blocksum[blockIdx.x] = red[0];
}

// ---------------- kernel 4b: final scalar ----------------
__global__ void finalize2_kernel(float* __restrict__ out) {
    int t = threadIdx.x;   // 32 threads
    float v = g_blocksum[t];
#pragma unroll
    for (int o = 16; o > 0; o >>= 1) v += __shfl_xor_sync(0xffffffffu, v, o);
    if (t == 0) out[0] = v / (float)NROWS;
}

// ---------------- launch ----------------
extern "C" void kernel_launch(void* const* d_in, const int* in_sizes, int n_in,
                              void* d_out, int out_size) {
    const float* p1 = (const float*)d_in[0];
    const float* p2 = (const float*)d_in[1];
    float* out = (float*)d_out;

    cudaFuncSetAttribute(sim_kernel, cudaFuncAttributeMaxDynamicSharedMemorySize, SMEM_BYTES);

    normalize_kernel<<<NROWS / 8, 256>>>(p1, p2);
    pos_kernel<<<NHALF / 8, 256>>>();
    sim_kernel<<<NTILES, 256, SMEM_BYTES>>>();
    finalize1_kernel<<<NROWS / 256, 256>>>();
    finalize2_kernel<<<1, 32>>>(out);
}